// round 7
// baseline (speedup 1.0000x reference)
#include <cuda_runtime.h>
#include <cuda_bf16.h>
#include <cstdint>

#define BATCH 16
#define CHAN  64
#define NPTS  65536
#define RES   (32*32*32)   // 32768

// ---------------- scratch (device globals; zero-initialized at load) --------
__device__ float        g_meansum[BATCH * 3];
__device__ unsigned int g_maxnorm[BATCH];          // float bits of max squared norm
__device__ int          g_voxidx[BATCH * NPTS];    // flat voxel index per point
__device__ int          g_counts[BATCH * RES];     // points per voxel
__device__ float        g_accum[(size_t)BATCH * RES * CHAN]; // [B, RES, C] sums

// ---------------- kernel 0: zero tiny per-batch stats ------------------------
__global__ void zero_small_kernel() {
    int i = threadIdx.x;
    if (i < BATCH * 3) g_meansum[i] = 0.0f;
    if (i < BATCH)     g_maxnorm[i] = 0u;
}

// ---------------- kernel 1: per-batch coordinate mean (sum) ------------------
__global__ void mean_kernel(const float* __restrict__ coords) {
    int b = blockIdx.y;
    const float* cb = coords + (size_t)b * 3 * NPTS;
    float sx = 0.f, sy = 0.f, sz = 0.f;
    for (int n = blockIdx.x * blockDim.x + threadIdx.x; n < NPTS;
         n += gridDim.x * blockDim.x) {
        sx += cb[n];
        sy += cb[NPTS + n];
        sz += cb[2 * NPTS + n];
    }
    for (int o = 16; o > 0; o >>= 1) {
        sx += __shfl_down_sync(0xffffffffu, sx, o);
        sy += __shfl_down_sync(0xffffffffu, sy, o);
        sz += __shfl_down_sync(0xffffffffu, sz, o);
    }
    __shared__ float shx[8], shy[8], shz[8];
    int warp = threadIdx.x >> 5, lane = threadIdx.x & 31;
    if (lane == 0) { shx[warp] = sx; shy[warp] = sy; shz[warp] = sz; }
    __syncthreads();
    if (threadIdx.x == 0) {
        float tx = 0.f, ty = 0.f, tz = 0.f;
        int nw = blockDim.x >> 5;
        for (int w = 0; w < nw; w++) { tx += shx[w]; ty += shy[w]; tz += shz[w]; }
        atomicAdd(&g_meansum[b * 3 + 0], tx);
        atomicAdd(&g_meansum[b * 3 + 1], ty);
        atomicAdd(&g_meansum[b * 3 + 2], tz);
    }
}

// ---------------- kernel 2: per-batch max squared norm of centered coords ----
__global__ void maxnorm_kernel(const float* __restrict__ coords) {
    int b = blockIdx.y;
    const float* cb = coords + (size_t)b * 3 * NPTS;
    const float inv_n = 1.0f / (float)NPTS;
    float mx = g_meansum[b * 3 + 0] * inv_n;
    float my = g_meansum[b * 3 + 1] * inv_n;
    float mz = g_meansum[b * 3 + 2] * inv_n;
    float best = 0.f;
    for (int n = blockIdx.x * blockDim.x + threadIdx.x; n < NPTS;
         n += gridDim.x * blockDim.x) {
        float dx = cb[n] - mx;
        float dy = cb[NPTS + n] - my;
        float dz = cb[2 * NPTS + n] - mz;
        best = fmaxf(best, dx * dx + dy * dy + dz * dz);
    }
    for (int o = 16; o > 0; o >>= 1)
        best = fmaxf(best, __shfl_down_sync(0xffffffffu, best, o));
    __shared__ float sh[8];
    int warp = threadIdx.x >> 5, lane = threadIdx.x & 31;
    if (lane == 0) sh[warp] = best;
    __syncthreads();
    if (threadIdx.x == 0) {
        float t = 0.f;
        int nw = blockDim.x >> 5;
        for (int w = 0; w < nw; w++) t = fmaxf(t, sh[w]);
        atomicMax(&g_maxnorm[b], __float_as_uint(t)); // nonneg floats: uint order ok
    }
}

// ---------------- kernel 3: per-point normalize, write norm_coords, count ----
__global__ void point_kernel(const float* __restrict__ coords,
                             float* __restrict__ norm_out) {
    int b = blockIdx.y;
    const float* cb = coords + (size_t)b * 3 * NPTS;
    float* nb = norm_out + (size_t)b * 3 * NPTS;
    const float inv_n = 1.0f / (float)NPTS;
    float mx = g_meansum[b * 3 + 0] * inv_n;
    float my = g_meansum[b * 3 + 1] * inv_n;
    float mz = g_meansum[b * 3 + 2] * inv_n;
    float inv_d = 1.0f / (sqrtf(__uint_as_float(g_maxnorm[b])) * 2.0f);

    for (int n = blockIdx.x * blockDim.x + threadIdx.x; n < NPTS;
         n += gridDim.x * blockDim.x) {
        float sx = ((cb[n]            - mx) * inv_d + 0.5f) * 32.0f;
        float sy = ((cb[NPTS + n]     - my) * inv_d + 0.5f) * 32.0f;
        float sz = ((cb[2 * NPTS + n] - mz) * inv_d + 0.5f) * 32.0f;
        sx = fminf(fmaxf(sx, 0.0f), 31.0f);
        sy = fminf(fmaxf(sy, 0.0f), 31.0f);
        sz = fminf(fmaxf(sz, 0.0f), 31.0f);
        nb[n]            = sx;
        nb[NPTS + n]     = sy;
        nb[2 * NPTS + n] = sz;
        int vx = (int)rintf(sx);   // round-half-even, matches jnp.round
        int vy = (int)rintf(sy);
        int vz = (int)rintf(sz);
        int idx = (vx << 10) + (vy << 5) + vz;
        g_voxidx[(b << 16) + n] = idx;
        atomicAdd(&g_counts[b * RES + idx], 1);
    }
}

// ---------------- kernel 4: scatter with v4 vector atomics (R3 mapping) ------
// thread = (b, 4-channel group cg, point n). Warp lanes share (b,cg), have
// consecutive n -> 4 coalesced 128B feature loads. One red.global.add.v4.f32
// into channel-contiguous scratch [B, RES, 64].
__global__ void scatter_kernel(const float* __restrict__ features) {
    int tid = blockIdx.x * blockDim.x + threadIdx.x;  // 16,777,216 threads
    int n  = tid & (NPTS - 1);
    int g  = tid >> 16;            // b*16 + cg
    int cg = g & 15;
    int b  = g >> 4;

    const float* f = features + ((size_t)(b * CHAN + cg * 4)) * NPTS + n;
    float f0 = f[0];
    float f1 = f[NPTS];
    float f2 = f[2 * NPTS];
    float f3 = f[3 * NPTS];

    int v = g_voxidx[(b << 16) + n];
    float* dst = g_accum + (((size_t)(b * RES + v)) << 6) + (cg << 2);
    asm volatile("red.global.add.v4.f32 [%0], {%1, %2, %3, %4};"
                 :: "l"(dst), "f"(f0), "f"(f1), "f"(f2), "f"(f3)
                 : "memory");
}

// ---------------- kernel 5: transpose [B,RES,C] -> out[B,C,RES], /cnt, rezero
__global__ void transpose_kernel(float* __restrict__ out) {
    __shared__ float tile[32][65];
    __shared__ float inv[32];
    int chunk = blockIdx.x;            // 0 .. BATCH*1024-1
    int b  = chunk >> 10;
    int v0 = (chunk & 1023) << 5;      // 32-voxel group

    float4* src = reinterpret_cast<float4*>(
        g_accum + (((size_t)(b * RES + v0)) << 6));
    const float4 z4 = make_float4(0.f, 0.f, 0.f, 0.f);
    #pragma unroll
    for (int k = 0; k < 2; k++) {
        int idx = threadIdx.x + (k << 8);   // 0..511 (32 vox x 16 float4)
        int vl = idx >> 4;
        int c4 = idx & 15;
        float4 val = src[vl * 16 + c4];
        src[vl * 16 + c4] = z4;             // re-zero for next replay
        int c = c4 << 2;
        tile[vl][c + 0] = val.x;
        tile[vl][c + 1] = val.y;
        tile[vl][c + 2] = val.z;
        tile[vl][c + 3] = val.w;
    }
    if (threadIdx.x < 32) {
        int ci = b * RES + v0 + threadIdx.x;
        int c = g_counts[ci];
        g_counts[ci] = 0;                   // re-zero for next replay
        inv[threadIdx.x] = 1.0f / (float)max(c, 1);
    }
    __syncthreads();

    int lane = threadIdx.x & 31;
    int wrp  = threadIdx.x >> 5;
    #pragma unroll
    for (int k = 0; k < 8; k++) {
        int c = wrp + (k << 3);            // 0..63
        out[((size_t)(b * CHAN + c)) * RES + v0 + lane] = tile[lane][c] * inv[lane];
    }
}

// ---------------- launcher ---------------------------------------------------
extern "C" void kernel_launch(void* const* d_in, const int* in_sizes, int n_in,
                              void* d_out, int out_size) {
    const float* features = (const float*)d_in[0];  // [B, C, N]
    const float* coords   = (const float*)d_in[1];  // [B, 3, N]
    float* out = (float*)d_out;                     // [B,C,32,32,32] ++ [B,3,N]
    float* norm_out = out + (size_t)BATCH * CHAN * RES;

    zero_small_kernel<<<1, 64>>>();

    dim3 grid_b(128, BATCH);
    mean_kernel<<<grid_b, 256>>>(coords);
    maxnorm_kernel<<<grid_b, 256>>>(coords);
    point_kernel<<<grid_b, 256>>>(coords, norm_out);

    scatter_kernel<<<65536, 256>>>(features);       // 16.8M threads, v4 reds

    transpose_kernel<<<BATCH * 1024, 256>>>(out);
}

// round 8
// speedup vs baseline: 1.8548x; 1.8548x over previous
#include <cuda_runtime.h>
#include <cuda_bf16.h>
#include <cstdint>

#define BATCH 16
#define CHAN  64
#define NPTS  65536
#define RES   (32*32*32)   // 32768

// ---------------- scratch (device globals; no allocations allowed) ----------
__device__ float        g_mean[BATCH * 3];         // per-batch mean (final)
__device__ float        g_invd[BATCH];             // 1/(2*max_norm)
__device__ int          g_voxidx[BATCH * NPTS];    // flat voxel index per point
__device__ int          g_counts[BATCH * RES];     // points per voxel
__device__ float        g_accum[(size_t)BATCH * RES * CHAN]; // [B, RES, C] sums

// ---------------- kernel 0: zero counts + stats ------------------------------
__global__ void zero_counts_kernel() {
    int i = blockIdx.x * blockDim.x + threadIdx.x;   // 131072 threads
    reinterpret_cast<int4*>(g_counts)[i] = make_int4(0, 0, 0, 0);
}

// ---------------- kernel 1: fused per-batch mean + max-norm ------------------
// one block of 1024 threads per batch; two passes with block-level reduction.
__global__ void meanmax_kernel(const float* __restrict__ coords) {
    int b = blockIdx.x;
    const float* cb = coords + (size_t)b * 3 * NPTS;
    __shared__ float shx[32], shy[32], shz[32];
    __shared__ float s_mx, s_my, s_mz;
    int warp = threadIdx.x >> 5, lane = threadIdx.x & 31;

    // pass 1: sum
    float sx = 0.f, sy = 0.f, sz = 0.f;
    for (int n = threadIdx.x; n < NPTS; n += 1024) {
        sx += cb[n];
        sy += cb[NPTS + n];
        sz += cb[2 * NPTS + n];
    }
    for (int o = 16; o > 0; o >>= 1) {
        sx += __shfl_down_sync(0xffffffffu, sx, o);
        sy += __shfl_down_sync(0xffffffffu, sy, o);
        sz += __shfl_down_sync(0xffffffffu, sz, o);
    }
    if (lane == 0) { shx[warp] = sx; shy[warp] = sy; shz[warp] = sz; }
    __syncthreads();
    if (threadIdx.x == 0) {
        float tx = 0.f, ty = 0.f, tz = 0.f;
        for (int w = 0; w < 32; w++) { tx += shx[w]; ty += shy[w]; tz += shz[w]; }
        const float inv_n = 1.0f / (float)NPTS;
        s_mx = tx * inv_n; s_my = ty * inv_n; s_mz = tz * inv_n;
        g_mean[b * 3 + 0] = s_mx;
        g_mean[b * 3 + 1] = s_my;
        g_mean[b * 3 + 2] = s_mz;
    }
    __syncthreads();
    float mx = s_mx, my = s_my, mz = s_mz;

    // pass 2: max squared norm (coords now L2-hot)
    float best = 0.f;
    for (int n = threadIdx.x; n < NPTS; n += 1024) {
        float dx = cb[n] - mx;
        float dy = cb[NPTS + n] - my;
        float dz = cb[2 * NPTS + n] - mz;
        best = fmaxf(best, dx * dx + dy * dy + dz * dz);
    }
    for (int o = 16; o > 0; o >>= 1)
        best = fmaxf(best, __shfl_down_sync(0xffffffffu, best, o));
    if (lane == 0) shx[warp] = best;
    __syncthreads();
    if (threadIdx.x == 0) {
        float t = 0.f;
        for (int w = 0; w < 32; w++) t = fmaxf(t, shx[w]);
        g_invd[b] = 1.0f / (sqrtf(t) * 2.0f);
    }
}

// ---------------- kernel 2: per-point normalize, write norm_coords, count ----
__global__ void point_kernel(const float* __restrict__ coords,
                             float* __restrict__ norm_out) {
    int b = blockIdx.y;
    const float* cb = coords + (size_t)b * 3 * NPTS;
    float* nb = norm_out + (size_t)b * 3 * NPTS;
    float mx = g_mean[b * 3 + 0];
    float my = g_mean[b * 3 + 1];
    float mz = g_mean[b * 3 + 2];
    float inv_d = g_invd[b];

    for (int n = blockIdx.x * blockDim.x + threadIdx.x; n < NPTS;
         n += gridDim.x * blockDim.x) {
        float sx = ((cb[n]            - mx) * inv_d + 0.5f) * 32.0f;
        float sy = ((cb[NPTS + n]     - my) * inv_d + 0.5f) * 32.0f;
        float sz = ((cb[2 * NPTS + n] - mz) * inv_d + 0.5f) * 32.0f;
        sx = fminf(fmaxf(sx, 0.0f), 31.0f);
        sy = fminf(fmaxf(sy, 0.0f), 31.0f);
        sz = fminf(fmaxf(sz, 0.0f), 31.0f);
        nb[n]            = sx;
        nb[NPTS + n]     = sy;
        nb[2 * NPTS + n] = sz;
        int vx = (int)rintf(sx);   // round-half-even, matches jnp.round
        int vy = (int)rintf(sy);
        int vz = (int)rintf(sz);
        int idx = (vx << 10) + (vy << 5) + vz;
        g_voxidx[(b << 16) + n] = idx;
        atomicAdd(&g_counts[b * RES + idx], 1);
    }
}

// ---------------- kernel 3: zero accum (installs lines in L2 pre-scatter) ----
__global__ void zero_accum_kernel() {
    int i = blockIdx.x * blockDim.x + threadIdx.x;   // 8,388,608 threads
    reinterpret_cast<float4*>(g_accum)[i] = make_float4(0.f, 0.f, 0.f, 0.f);
}

// ---------------- kernel 4: scatter with v4 vector atomics (R3 mapping) ------
__global__ void scatter_kernel(const float* __restrict__ features) {
    int tid = blockIdx.x * blockDim.x + threadIdx.x;  // 16,777,216 threads
    int n  = tid & (NPTS - 1);
    int g  = tid >> 16;            // b*16 + cg
    int cg = g & 15;
    int b  = g >> 4;

    const float* f = features + ((size_t)(b * CHAN + cg * 4)) * NPTS + n;
    float f0 = f[0];
    float f1 = f[NPTS];
    float f2 = f[2 * NPTS];
    float f3 = f[3 * NPTS];

    int v = g_voxidx[(b << 16) + n];
    float* dst = g_accum + (((size_t)(b * RES + v)) << 6) + (cg << 2);
    asm volatile("red.global.add.v4.f32 [%0], {%1, %2, %3, %4};"
                 :: "l"(dst), "f"(f0), "f"(f1), "f"(f2), "f"(f3)
                 : "memory");
}

// ---------------- kernel 5: transpose [B,RES,C] -> out[B,C,RES] with divide --
__global__ void transpose_kernel(float* __restrict__ out) {
    __shared__ float tile[32][65];
    __shared__ float inv[32];
    int chunk = blockIdx.x;            // 0 .. BATCH*1024-1
    int b  = chunk >> 10;
    int v0 = (chunk & 1023) << 5;      // 32-voxel group

    const float* src = g_accum + (((size_t)(b * RES + v0)) << 6);
    #pragma unroll
    for (int k = 0; k < 8; k++) {
        int idx = threadIdx.x + (k << 8);   // 0..2047
        int c  = idx & 63;
        int vl = idx >> 6;
        tile[vl][c] = src[(size_t)(vl << 6) + c];
    }
    if (threadIdx.x < 32) {
        int c = g_counts[b * RES + v0 + threadIdx.x];
        inv[threadIdx.x] = 1.0f / (float)max(c, 1);
    }
    __syncthreads();

    int lane = threadIdx.x & 31;
    int wrp  = threadIdx.x >> 5;
    #pragma unroll
    for (int k = 0; k < 8; k++) {
        int c = wrp + (k << 3);            // 0..63
        out[((size_t)(b * CHAN + c)) * RES + v0 + lane] = tile[lane][c] * inv[lane];
    }
}

// ---------------- launcher ---------------------------------------------------
extern "C" void kernel_launch(void* const* d_in, const int* in_sizes, int n_in,
                              void* d_out, int out_size) {
    const float* features = (const float*)d_in[0];  // [B, C, N]
    const float* coords   = (const float*)d_in[1];  // [B, 3, N]
    float* out = (float*)d_out;                     // [B,C,32,32,32] ++ [B,3,N]
    float* norm_out = out + (size_t)BATCH * CHAN * RES;

    zero_counts_kernel<<<512, 256>>>();             // counts (2MB)
    meanmax_kernel<<<BATCH, 1024>>>(coords);        // fused mean + max-norm

    dim3 grid_b(128, BATCH);
    point_kernel<<<grid_b, 256>>>(coords, norm_out);

    zero_accum_kernel<<<32768, 256>>>();            // install accum in L2
    scatter_kernel<<<65536, 256>>>(features);       // 16.8M threads, v4 reds

    transpose_kernel<<<BATCH * 1024, 256>>>(out);
}

// round 9
// speedup vs baseline: 1.9887x; 1.0722x over previous
#include <cuda_runtime.h>
#include <cuda_bf16.h>
#include <cstdint>

#define BATCH 16
#define HALF  8
#define CHAN  64
#define NPTS  65536
#define RES   (32*32*32)   // 32768

// ---------------- scratch (device globals; no allocations allowed) ----------
__device__ float        g_meansum[BATCH * 3];
__device__ unsigned int g_maxnorm[BATCH];          // float bits of max squared norm
__device__ int          g_voxidx[BATCH * NPTS];    // flat voxel index per point
__device__ int          g_counts[BATCH * RES];     // points per voxel
__device__ float        g_accum[(size_t)HALF * RES * CHAN]; // [8, RES, C] sums

// ---------------- kernel 0: zero counts + stats ------------------------------
__global__ void zero_counts_kernel() {
    int i = blockIdx.x * blockDim.x + threadIdx.x;   // 65536 threads x 2 int4
    reinterpret_cast<int4*>(g_counts)[i]         = make_int4(0, 0, 0, 0);
    reinterpret_cast<int4*>(g_counts)[i + 65536] = make_int4(0, 0, 0, 0);
    if (i < BATCH * 3) g_meansum[i] = 0.0f;
    if (i < BATCH)     g_maxnorm[i] = 0u;
}

// ---------------- kernel 1: per-batch coordinate mean (sum) ------------------
__global__ void mean_kernel(const float* __restrict__ coords) {
    int b = blockIdx.y;
    const float* cb = coords + (size_t)b * 3 * NPTS;
    float sx = 0.f, sy = 0.f, sz = 0.f;
    for (int n = blockIdx.x * blockDim.x + threadIdx.x; n < NPTS;
         n += gridDim.x * blockDim.x) {
        sx += cb[n];
        sy += cb[NPTS + n];
        sz += cb[2 * NPTS + n];
    }
    for (int o = 16; o > 0; o >>= 1) {
        sx += __shfl_down_sync(0xffffffffu, sx, o);
        sy += __shfl_down_sync(0xffffffffu, sy, o);
        sz += __shfl_down_sync(0xffffffffu, sz, o);
    }
    __shared__ float shx[8], shy[8], shz[8];
    int warp = threadIdx.x >> 5, lane = threadIdx.x & 31;
    if (lane == 0) { shx[warp] = sx; shy[warp] = sy; shz[warp] = sz; }
    __syncthreads();
    if (threadIdx.x == 0) {
        float tx = 0.f, ty = 0.f, tz = 0.f;
        int nw = blockDim.x >> 5;
        for (int w = 0; w < nw; w++) { tx += shx[w]; ty += shy[w]; tz += shz[w]; }
        atomicAdd(&g_meansum[b * 3 + 0], tx);
        atomicAdd(&g_meansum[b * 3 + 1], ty);
        atomicAdd(&g_meansum[b * 3 + 2], tz);
    }
}

// ---------------- kernel 2: per-batch max squared norm of centered coords ----
__global__ void maxnorm_kernel(const float* __restrict__ coords) {
    int b = blockIdx.y;
    const float* cb = coords + (size_t)b * 3 * NPTS;
    const float inv_n = 1.0f / (float)NPTS;
    float mx = g_meansum[b * 3 + 0] * inv_n;
    float my = g_meansum[b * 3 + 1] * inv_n;
    float mz = g_meansum[b * 3 + 2] * inv_n;
    float best = 0.f;
    for (int n = blockIdx.x * blockDim.x + threadIdx.x; n < NPTS;
         n += gridDim.x * blockDim.x) {
        float dx = cb[n] - mx;
        float dy = cb[NPTS + n] - my;
        float dz = cb[2 * NPTS + n] - mz;
        best = fmaxf(best, dx * dx + dy * dy + dz * dz);
    }
    for (int o = 16; o > 0; o >>= 1)
        best = fmaxf(best, __shfl_down_sync(0xffffffffu, best, o));
    __shared__ float sh[8];
    int warp = threadIdx.x >> 5, lane = threadIdx.x & 31;
    if (lane == 0) sh[warp] = best;
    __syncthreads();
    if (threadIdx.x == 0) {
        float t = 0.f;
        int nw = blockDim.x >> 5;
        for (int w = 0; w < nw; w++) t = fmaxf(t, sh[w]);
        atomicMax(&g_maxnorm[b], __float_as_uint(t)); // nonneg floats: uint order ok
    }
}

// ---------------- kernel 3: per-point normalize, write norm_coords, count ----
__global__ void point_kernel(const float* __restrict__ coords,
                             float* __restrict__ norm_out) {
    int b = blockIdx.y;
    const float* cb = coords + (size_t)b * 3 * NPTS;
    float* nb = norm_out + (size_t)b * 3 * NPTS;
    const float inv_n = 1.0f / (float)NPTS;
    float mx = g_meansum[b * 3 + 0] * inv_n;
    float my = g_meansum[b * 3 + 1] * inv_n;
    float mz = g_meansum[b * 3 + 2] * inv_n;
    float inv_d = 1.0f / (sqrtf(__uint_as_float(g_maxnorm[b])) * 2.0f);

    for (int n = blockIdx.x * blockDim.x + threadIdx.x; n < NPTS;
         n += gridDim.x * blockDim.x) {
        float sx = ((cb[n]            - mx) * inv_d + 0.5f) * 32.0f;
        float sy = ((cb[NPTS + n]     - my) * inv_d + 0.5f) * 32.0f;
        float sz = ((cb[2 * NPTS + n] - mz) * inv_d + 0.5f) * 32.0f;
        sx = fminf(fmaxf(sx, 0.0f), 31.0f);
        sy = fminf(fmaxf(sy, 0.0f), 31.0f);
        sz = fminf(fmaxf(sz, 0.0f), 31.0f);
        nb[n]            = sx;
        nb[NPTS + n]     = sy;
        nb[2 * NPTS + n] = sz;
        int vx = (int)rintf(sx);   // round-half-even, matches jnp.round
        int vy = (int)rintf(sy);
        int vz = (int)rintf(sz);
        int idx = (vx << 10) + (vy << 5) + vz;
        g_voxidx[(b << 16) + n] = idx;
        atomicAdd(&g_counts[b * RES + idx], 1);
    }
}

// ---------------- kernel 4: zero accum half (installs 67MB in L2) ------------
__global__ void zero_accum_kernel() {
    int i = blockIdx.x * blockDim.x + threadIdx.x;   // 2,097,152 threads x 2
    float4 z = make_float4(0.f, 0.f, 0.f, 0.f);
    reinterpret_cast<float4*>(g_accum)[i]             = z;
    reinterpret_cast<float4*>(g_accum)[i + 2097152]   = z;
}

// ---------------- kernel 5: scatter half with v4 vector atomics --------------
// thread = (bl, cg, n); warp lanes share (bl,cg), consecutive n.
__global__ void scatter_kernel(const float* __restrict__ features, int b0) {
    int tid = blockIdx.x * blockDim.x + threadIdx.x;  // 8,388,608 threads
    int n  = tid & (NPTS - 1);
    int g  = tid >> 16;            // bl*16 + cg
    int cg = g & 15;
    int bl = g >> 4;               // 0..7
    int b  = b0 + bl;

    const float* f = features + ((size_t)(b * CHAN + cg * 4)) * NPTS + n;
    float f0 = f[0];
    float f1 = f[NPTS];
    float f2 = f[2 * NPTS];
    float f3 = f[3 * NPTS];

    int v = g_voxidx[(b << 16) + n];
    float* dst = g_accum + (((size_t)(bl * RES + v)) << 6) + (cg << 2);
    asm volatile("red.global.add.v4.f32 [%0], {%1, %2, %3, %4};"
                 :: "l"(dst), "f"(f0), "f"(f1), "f"(f2), "f"(f3)
                 : "memory");
}

// ---------------- kernel 6: transpose half [8,RES,C] -> out[B,C,RES], /cnt ---
__global__ void transpose_kernel(float* __restrict__ out, int b0) {
    __shared__ float tile[32][65];
    __shared__ float inv[32];
    int chunk = blockIdx.x;            // 0 .. HALF*1024-1
    int bl = chunk >> 10;
    int b  = b0 + bl;
    int v0 = (chunk & 1023) << 5;      // 32-voxel group

    const float* src = g_accum + (((size_t)(bl * RES + v0)) << 6);
    #pragma unroll
    for (int k = 0; k < 8; k++) {
        int idx = threadIdx.x + (k << 8);   // 0..2047
        int c  = idx & 63;
        int vl = idx >> 6;
        tile[vl][c] = src[(size_t)(vl << 6) + c];
    }
    if (threadIdx.x < 32) {
        int c = g_counts[b * RES + v0 + threadIdx.x];
        inv[threadIdx.x] = 1.0f / (float)max(c, 1);
    }
    __syncthreads();

    int lane = threadIdx.x & 31;
    int wrp  = threadIdx.x >> 5;
    #pragma unroll
    for (int k = 0; k < 8; k++) {
        int c = wrp + (k << 3);            // 0..63
        out[((size_t)(b * CHAN + c)) * RES + v0 + lane] = tile[lane][c] * inv[lane];
    }
}

// ---------------- launcher ---------------------------------------------------
extern "C" void kernel_launch(void* const* d_in, const int* in_sizes, int n_in,
                              void* d_out, int out_size) {
    const float* features = (const float*)d_in[0];  // [B, C, N]
    const float* coords   = (const float*)d_in[1];  // [B, 3, N]
    float* out = (float*)d_out;                     // [B,C,32,32,32] ++ [B,3,N]
    float* norm_out = out + (size_t)BATCH * CHAN * RES;

    zero_counts_kernel<<<256, 256>>>();

    dim3 grid_b(32, BATCH);
    mean_kernel<<<grid_b, 256>>>(coords);
    maxnorm_kernel<<<grid_b, 256>>>(coords);
    dim3 grid_p(128, BATCH);
    point_kernel<<<grid_p, 256>>>(coords, norm_out);

    // two halves: 67MB accum stays L2-resident through scatter + transpose
    zero_accum_kernel<<<8192, 256>>>();
    scatter_kernel<<<32768, 256>>>(features, 0);
    transpose_kernel<<<HALF * 1024, 256>>>(out, 0);

    zero_accum_kernel<<<8192, 256>>>();
    scatter_kernel<<<32768, 256>>>(features, HALF);
    transpose_kernel<<<HALF * 1024, 256>>>(out, HALF);
}